// round 10
// baseline (speedup 1.0000x reference)
#include <cuda_runtime.h>
#include <cuda_fp16.h>
#include <math.h>
#include <stdint.h>

// out = LayerNorm(Re(FFT(x, axis=-1))), x: (4,4096,2048) fp32.
// Radix-2 split of the folded cosine transform:
//   s[c] = x[c]+x[2048-c] (c=1..1023), s[1024]=x[1024]; c=0 dropped (== mean)
//   Se[0]=s[1024], Se[j]=s[2j] (j=1..511);  Be[k][0]=(-1)^k, Be[k][j]=cospi(kj/512)
//   So[d]=s[2d+1] (d=0..511);               Bo[k][d]=cospi(k(2d+1)/1024)
//   E[k]=Se.Be[k], O[k]=So.Bo[k];  y-mu: [k]=E+O, [1024-k]=E-O (k=0..511)
//   y[512]-mu = sum_j Se[j](-1)^j (prep, closed form); mirror y[2048-k]=y[k]
//   var = 0.5*(sum x^2 + sum x[c]x[(2048-c)%2048]) - x[0]^2
// GEMM: M=16384, K=512 x2 phases, N=512, fp16/fp32 mma.sync.
// CTA tile 128m x 64n, 8 warps as 4m x 2n (warp 32x32 -> 0.5 LDSM.x4/MMA),
// 4-stage cp.async, 2 CTAs/SM.

#define ROWS 16384
#define CDIM 2048
#define BM   128
#define BNK  64
#define BKC  64
#define NT   16          // chunks: 8 E + 8 O
#define STAGES 4
#define TBLOCKS 2048     // table-init blocks (1 half per thread)
#define EPS  1e-5f

__device__ __half g_S[(size_t)ROWS * 1024];  // [m][0..511]=Se, [512..1023]=So
__device__ __half g_T[(size_t)512 * 1024];   // [k][0..511]=Be, [512..1023]=Bo
__device__ float  g_rs[ROWS];

__device__ __forceinline__ uint32_t smem_u32(const void* p) {
    uint32_t a;
    asm("{ .reg .u64 t; cvta.to.shared.u64 t, %1; cvt.u32.u64 %0, t; }" : "=r"(a) : "l"(p));
    return a;
}
__device__ __forceinline__ void cp16(uint32_t s, const void* g) {
    asm volatile("cp.async.cg.shared.global [%0], [%1], 16;" :: "r"(s), "l"(g) : "memory");
}
#define CP_COMMIT() asm volatile("cp.async.commit_group;" ::: "memory")

__device__ __forceinline__ void ldm_x4(uint32_t* r, uint32_t a) {
    asm volatile("ldmatrix.sync.aligned.m8n8.x4.shared.b16 {%0,%1,%2,%3}, [%4];"
                 : "=r"(r[0]), "=r"(r[1]), "=r"(r[2]), "=r"(r[3]) : "r"(a));
}
__device__ __forceinline__ void mma16816(float* c, const uint32_t* a, const uint32_t* b) {
    asm volatile("mma.sync.aligned.m16n8k16.row.col.f32.f16.f16.f32 "
                 "{%0,%1,%2,%3}, {%4,%5,%6,%7}, {%8,%9}, {%0,%1,%2,%3};"
                 : "+f"(c[0]), "+f"(c[1]), "+f"(c[2]), "+f"(c[3])
                 : "r"(a[0]), "r"(a[1]), "r"(a[2]), "r"(a[3]), "r"(b[0]), "r"(b[1]));
}

// ---------------------------------------------------------------- prep + table
// blocks [0,ROWS): register-only fold/stats, 1 row per 256-thread block.
// blocks [ROWS,ROWS+TBLOCKS): tables. Args of cospif exact in fp32 (<2^24).
__global__ __launch_bounds__(256) void prep_kernel(const float* __restrict__ x,
                                                   const float* __restrict__ gamma,
                                                   const float* __restrict__ beta,
                                                   float* __restrict__ out) {
    if (blockIdx.x >= ROWS) {
        int idx = (blockIdx.x - ROWS) * 256 + threadIdx.x;   // < 512*1024
        int k = idx >> 10;
        int j = idx & 1023;
        float v;
        if (j < 512) {
            int jj = j ? j : 512;                 // j=0 column: cospi(k) = (-1)^k
            v = cospif((float)(k * jj) * (1.0f / 512.0f));
        } else {
            v = cospif((float)(k * (2 * (j - 512) + 1)) * (1.0f / 1024.0f));
        }
        g_T[idx] = __float2half(v);
        return;
    }

    __shared__ float w1[8], w2[8], w3[8];
    const int row = blockIdx.x;
    const int tid = threadIdx.x;
    const float* xr = x + (size_t)row * CDIM;
    const float4* x4 = (const float4*)xr;

    float4 f4 = x4[tid];          // x[4t .. 4t+3]       (covers 0..1023)
    float4 b4 = x4[511 - tid];    // x[2044-4t..2047-4t] (covers 1024..2047)
    float xm = 0.0f, x1024 = 0.0f;
    if (tid > 0) xm = xr[2048 - 4 * tid];
    else         x1024 = xr[1024];

    float sumsq = f4.x * f4.x + f4.y * f4.y + f4.z * f4.z + f4.w * f4.w
                + b4.x * b4.x + b4.y * b4.y + b4.z * b4.z + b4.w * b4.w;

    // folds: s[c] = x[c] + x[2048-c]
    float s0 = f4.x + xm;      // s[4t]   (t>0)
    float s1 = f4.y + b4.w;    // s[4t+1]
    float s2 = f4.z + b4.z;    // s[4t+2]
    float s3 = f4.w + b4.y;    // s[4t+3]

    float r, e;
    __half2 he, ho;
    if (tid > 0) {
        r = f4.x * xm + f4.y * b4.w + f4.z * b4.z + f4.w * b4.y;
        e = s0 - s2;
        he = __floats2half2_rn(s0, s2);            // Se[2t], Se[2t+1]
    } else {
        r = f4.y * b4.w + f4.z * b4.z + f4.w * b4.y
          + 0.5f * (f4.x * f4.x + x1024 * x1024);
        e = x1024 - s2;
        he = __floats2half2_rn(x1024, s2);         // Se[0]=s[1024], Se[1]=s[2]
    }
    ho = __floats2half2_rn(s1, s3);                // So[2t], So[2t+1]

    __half* Sr = g_S + (size_t)row * 1024;
    *(__half2*)(Sr + 2 * tid) = he;
    *(__half2*)(Sr + 512 + 2 * tid) = ho;

    #pragma unroll
    for (int o = 16; o > 0; o >>= 1) {
        sumsq += __shfl_xor_sync(0xffffffffu, sumsq, o);
        r     += __shfl_xor_sync(0xffffffffu, r, o);
        e     += __shfl_xor_sync(0xffffffffu, e, o);
    }
    if ((tid & 31) == 0) { w1[tid >> 5] = sumsq; w2[tid >> 5] = r; w3[tid >> 5] = e; }
    __syncthreads();
    if (tid == 0) {
        float a = 0.0f, rr = 0.0f, e5 = 0.0f;
        #pragma unroll
        for (int i = 0; i < 8; i++) { a += w1[i]; rr += w2[i]; e5 += w3[i]; }
        float mu = f4.x;                       // x[0]
        float var = 0.5f * (a + 2.0f * rr) - mu * mu;
        float rs = rsqrtf(var + EPS);
        g_rs[row] = rs;
        float z = e5 * rs;                     // y[512]-mu
        float* orow = out + (size_t)row * CDIM;
        orow[512]  = z * gamma[512]  + beta[512];
        orow[1536] = z * gamma[1536] + beta[1536];
    }
}

// ---------------------------------------------------------------- GEMM + LN
// stage: A 128x64 fp16 (16KB) + B 64x64 fp16 (8KB) = 24KB; rows 128B, xor swizzle
#define STAGE_BYTES 24576
#define SMEM_SZ (STAGES * STAGE_BYTES)

__global__ __launch_bounds__(256, 2) void gemm_ln_kernel(const float* __restrict__ gamma,
                                                         const float* __restrict__ beta,
                                                         float* __restrict__ out) {
    extern __shared__ __align__(1024) uint8_t smem[];
    const uint32_t sbase = smem_u32(smem);
    const int tid = threadIdx.x;
    const int wid = tid >> 5;
    const int lane = tid & 31;
    const int m0 = blockIdx.y * BM;
    const int k0 = blockIdx.x * BNK;     // k-column tile base (0..511)

    // ---- producers: A 128 rows x 4 chunks/thread; B 64 rows x 2 chunks/thread
    const int arow = tid >> 1;
    const int ac0 = (tid & 1) * 4;
    const __half* gA = g_S + (size_t)(m0 + arow) * 1024 + ac0 * 8;
    const uint32_t aso = (uint32_t)arow * 128u;
    const int arx = arow & 7;
    const int brow = tid >> 2;
    const int bc0 = (tid & 3) * 2;
    const __half* gB = g_T + (size_t)(k0 + brow) * 1024 + bc0 * 8;
    const uint32_t bso = (uint32_t)brow * 128u;
    const int brx = brow & 7;

    // ---- consumers: 8 warps = 4 (m) x 2 (n); warp tile 32m x 32n
    const int wm = wid & 3;
    const int wn = wid >> 2;
    uint32_t rowa_off[2];
    {
        int rbase = wm * 32 + (lane & 15);
        rowa_off[0] = (uint32_t)rbase * 128u;
        rowa_off[1] = (uint32_t)(rbase + 16) * 128u;
    }
    const int rxa = lane & 7;
    const int csel_a = lane >> 4;
    uint32_t rowb_off[2];
    {
        int nb = wn * 32 + ((lane >> 4) << 3) + (lane & 7);
        rowb_off[0] = (uint32_t)nb * 128u;
        rowb_off[1] = (uint32_t)(nb + 16) * 128u;
    }
    const int rxb = lane & 7;
    const int csel_b = (lane >> 3) & 1;

    float accE[2][4][4], accO[2][4][4];
    #pragma unroll
    for (int i = 0; i < 2; i++)
        #pragma unroll
        for (int j = 0; j < 4; j++)
            #pragma unroll
            for (int r = 0; r < 4; r++) { accE[i][j][r] = 0.0f; accO[i][j][r] = 0.0f; }

    auto load_stage = [&](int stage, int t) {
        uint32_t sA = sbase + (uint32_t)stage * STAGE_BYTES;
        uint32_t sB = sA + 16384u;
        int koff = (t >> 3) * 512 + (t & 7) * BKC;    // phase*512 + kc*64
        const __half* pa = gA + koff;
        const __half* pb = gB + koff;
        #pragma unroll
        for (int i = 0; i < 4; i++)
            cp16(sA + aso + (uint32_t)(((ac0 + i) ^ arx) << 4), pa + i * 8);
        #pragma unroll
        for (int i = 0; i < 2; i++)
            cp16(sB + bso + (uint32_t)(((bc0 + i) ^ brx) << 4), pb + i * 8);
        CP_COMMIT();
    };

    load_stage(0, 0);
    load_stage(1, 1);
    load_stage(2, 2);

    for (int t = 0; t < NT; t++) {
        if (t < NT - 2)       asm volatile("cp.async.wait_group 2;" ::: "memory");
        else if (t == NT - 2) asm volatile("cp.async.wait_group 1;" ::: "memory");
        else                  asm volatile("cp.async.wait_group 0;" ::: "memory");
        __syncthreads();
        if (t + 3 < NT) load_stage((t + 3) & (STAGES - 1), t + 3);

        uint32_t stA = sbase + (uint32_t)(t & (STAGES - 1)) * STAGE_BYTES;
        uint32_t stB = stA + 16384u;

        #pragma unroll
        for (int ks = 0; ks < 4; ks++) {
            uint32_t a[2][4], b[2][4];
            int cha = (2 * ks + csel_a) ^ rxa;
            ldm_x4(a[0], stA + rowa_off[0] + (uint32_t)(cha << 4));
            ldm_x4(a[1], stA + rowa_off[1] + (uint32_t)(cha << 4));
            int chb = (2 * ks + csel_b) ^ rxb;
            ldm_x4(b[0], stB + rowb_off[0] + (uint32_t)(chb << 4));
            ldm_x4(b[1], stB + rowb_off[1] + (uint32_t)(chb << 4));
            if (t < 8) {
                #pragma unroll
                for (int mf = 0; mf < 2; mf++) {
                    mma16816(accE[mf][0], a[mf], &b[0][0]);
                    mma16816(accE[mf][1], a[mf], &b[0][2]);
                    mma16816(accE[mf][2], a[mf], &b[1][0]);
                    mma16816(accE[mf][3], a[mf], &b[1][2]);
                }
            } else {
                #pragma unroll
                for (int mf = 0; mf < 2; mf++) {
                    mma16816(accO[mf][0], a[mf], &b[0][0]);
                    mma16816(accO[mf][1], a[mf], &b[0][2]);
                    mma16816(accO[mf][2], a[mf], &b[1][0]);
                    mma16816(accO[mf][3], a[mf], &b[1][2]);
                }
            }
        }
    }

    // ---- epilogue: butterfly + LN + 4-region store
    const int kw = k0 + wn * 32 + 2 * (lane & 3);
    #pragma unroll
    for (int nf = 0; nf < 4; nf++) {
        int k = kw + nf * 8;                       // even, 0..510
        float g0 = __ldg(gamma + k),     be0 = __ldg(beta + k);
        float g1 = __ldg(gamma + k + 1), be1 = __ldg(beta + k + 1);
        float gm1 = __ldg(gamma + 2047 - k), bm1 = __ldg(beta + 2047 - k);
        float gm0 = 0.0f, bm0 = 0.0f;
        if (k > 0) { gm0 = __ldg(gamma + 2048 - k); bm0 = __ldg(beta + 2048 - k); }
        float gb0 = __ldg(gamma + 1024 - k), bb0 = __ldg(beta + 1024 - k);
        float gb1 = __ldg(gamma + 1023 - k), bb1 = __ldg(beta + 1023 - k);
        float gf0 = __ldg(gamma + 1024 + k), bf0 = __ldg(beta + 1024 + k);
        float gf1 = __ldg(gamma + 1025 + k), bf1 = __ldg(beta + 1025 + k);
        #pragma unroll
        for (int mf = 0; mf < 2; mf++) {
            int r0 = m0 + wm * 32 + mf * 16 + (lane >> 2);
            #pragma unroll
            for (int rp = 0; rp < 2; rp++) {
                float* o = out + (size_t)(r0 + rp * 8) * CDIM;
                float rsv = g_rs[r0 + rp * 8];
                float E0 = accE[mf][nf][rp * 2],     O0 = accO[mf][nf][rp * 2];
                float E1 = accE[mf][nf][rp * 2 + 1], O1 = accO[mf][nf][rp * 2 + 1];
                float z0 = (E0 + O0) * rsv, z1 = (E1 + O1) * rsv;
                float w0 = (E0 - O0) * rsv, w1 = (E1 - O1) * rsv;
                *(float2*)(o + k) = make_float2(z0 * g0 + be0, z1 * g1 + be1);
                o[2047 - k] = z1 * gm1 + bm1;
                if (k > 0) o[2048 - k] = z0 * gm0 + bm0;
                o[1024 - k] = w0 * gb0 + bb0;
                o[1023 - k] = w1 * gb1 + bb1;
                if (k > 0) *(float2*)(o + 1024 + k) = make_float2(w0 * gf0 + bf0, w1 * gf1 + bf1);
                else       o[1025] = w1 * gf1 + bf1;
            }
        }
    }
}

// ---------------------------------------------------------------- launch
extern "C" void kernel_launch(void* const* d_in, const int* in_sizes, int n_in,
                              void* d_out, int out_size) {
    const float* x     = (const float*)d_in[0];
    const float* gamma = (const float*)d_in[1];
    const float* beta  = (const float*)d_in[2];
    float* out = (float*)d_out;

    prep_kernel<<<ROWS + TBLOCKS, 256>>>(x, gamma, beta, out);

    cudaFuncSetAttribute(gemm_ln_kernel, cudaFuncAttributeMaxDynamicSharedMemorySize, SMEM_SZ);
    dim3 grid(512 / BNK, ROWS / BM);   // (8, 128): k fastest -> A rows shared in L2
    gemm_ln_kernel<<<grid, 256, SMEM_SZ>>>(gamma, beta, out);
}

// round 11
// speedup vs baseline: 1.4253x; 1.4253x over previous
#include <cuda_runtime.h>
#include <math.h>
#include <stdint.h>

// out = LayerNorm(Re(FFT(x, axis=-1))), x: (4,4096,2048) fp32.
// One block per row. Pack x into z[n] = x[2n] + i*x[2n+1] (1024 complex),
// 1024-pt Stockham radix-4 DIF FFT (5 stages, natural order out), then
// real-FFT untangle:
//   E[k] = (Z[k] + conj(Z[-k]))/2,  O[k] = -i/2 (Z[k] - conj(Z[-k]))
//   y[k] = Re E + cos(pi k/1024) Re O + sin(pi k/1024) Im O   (k=0..1023)
//   y[1024] = Re Z[0] - Im Z[0];  y[2048-k] = y[k]
// LN: mu = x[0] (exact identity); var = mean(y^2) - mu^2 via block reduce.
// Twiddles from one table U[j] = exp(-i pi j/1024) (global init, smem copy):
//   stage twiddles w1 = U[2u], U[8(u>>2)], U[32(u>>4)], U[128(u>>6)], 1.
// Stages 0/1 write through bijective bank-spreading perms phi2/psi4.

#define ROWS 16384
#define CDIM 2048
#define EPS  1e-5f

__device__ float2 g_U[1024];

__global__ void initU_kernel() {
    int j = blockIdx.x * 256 + threadIdx.x;      // 0..1023
    float s, c;
    sincospif((float)j * (1.0f / 1024.0f), &s, &c);
    g_U[j] = make_float2(c, -s);                 // exp(-i pi j / 1024)
}

__device__ __forceinline__ float2 cmul(float2 a, float2 b) {
    return make_float2(fmaf(a.x, b.x, -a.y * b.y), fmaf(a.x, b.y, a.y * b.x));
}
__device__ __forceinline__ float2 cadd(float2 a, float2 b) { return make_float2(a.x + b.x, a.y + b.y); }
__device__ __forceinline__ float2 csub(float2 a, float2 b) { return make_float2(a.x - b.x, a.y - b.y); }

// radix-4 DIF butterfly: y_e = w1^e * (sum_q in_q * i^{-qe})
__device__ __forceinline__ void bf4(float2 a, float2 b, float2 c, float2 d,
                                    float2 w1, bool tw,
                                    float2& y0, float2& y1, float2& y2, float2& y3) {
    float2 t0 = cadd(a, c), t1 = csub(a, c);
    float2 t2 = cadd(b, d);
    float2 bd = csub(b, d);
    float2 t3 = make_float2(bd.y, -bd.x);        // -i*(b-d)
    y0 = cadd(t0, t2);
    float2 u1 = cadd(t1, t3);
    float2 u2 = csub(t0, t2);
    float2 u3 = csub(t1, t3);
    if (tw) {
        float2 w2 = cmul(w1, w1);
        float2 w3 = cmul(w2, w1);
        y1 = cmul(w1, u1);
        y2 = cmul(w2, u2);
        y3 = cmul(w3, u3);
    } else {
        y1 = u1; y2 = u2; y3 = u3;
    }
}

// Bank-spreading bijections for the two small-m stages (correct for ANY bijection).
__device__ __forceinline__ int phi2(int i) {     // stage-0 out: i = 4u + q
    return ((i & 3) << 8) | ((i >> 2) ^ ((i & 3) << 3));
}
__device__ __forceinline__ int psi4(int i) {     // stage-1 out: i = k + 4q + 16j
    int k = i & 3, q = (i >> 2) & 3;
    return (q << 8) | ((i >> 6) << 4) | ((((i >> 4) ^ q) & 3) << 2) | k;
}

__global__ __launch_bounds__(256) void fft_ln_kernel(const float* __restrict__ x,
                                                     const float* __restrict__ gamma,
                                                     const float* __restrict__ beta,
                                                     float* __restrict__ out) {
    __shared__ float2 bufA[1024];
    __shared__ float2 bufB[1024];
    __shared__ float2 Us[1024];
    __shared__ float red[8];
    __shared__ float s_stats[2];                 // [0]=mu, [1]=rs

    const int t = threadIdx.x;
    const int row = blockIdx.x;
    const float2* z = (const float2*)(x + (size_t)row * CDIM);

    #pragma unroll
    for (int q = 0; q < 4; q++) Us[t + 256 * q] = g_U[t + 256 * q];

    // stage 0 (l=256, m=1): gmem -> bufB[phi2]
    float2 a = z[t], b = z[t + 256], c = z[t + 512], d = z[t + 768];
    if (t == 0) s_stats[0] = a.x;                // mu = x[0]
    __syncthreads();                             // Us visible
    {
        float2 y0, y1, y2, y3;
        bf4(a, b, c, d, Us[2 * t], true, y0, y1, y2, y3);
        int base = 4 * t;
        bufB[phi2(base + 0)] = y0;
        bufB[phi2(base + 1)] = y1;
        bufB[phi2(base + 2)] = y2;
        bufB[phi2(base + 3)] = y3;
    }
    __syncthreads();

    // stage 1 (l=64, m=4): bufB[phi2] -> bufA[psi4]
    {
        float2 a1 = bufB[phi2(t)],       b1 = bufB[phi2(t + 256)];
        float2 c1 = bufB[phi2(t + 512)], d1 = bufB[phi2(t + 768)];
        float2 y0, y1, y2, y3;
        bf4(a1, b1, c1, d1, Us[8 * (t >> 2)], true, y0, y1, y2, y3);
        int base = (t & 3) + 16 * (t >> 2);      // k + 16 j
        bufA[psi4(base + 0)]  = y0;
        bufA[psi4(base + 4)]  = y1;
        bufA[psi4(base + 8)]  = y2;
        bufA[psi4(base + 12)] = y3;
    }
    __syncthreads();

    // stage 2 (l=16, m=16): bufA[psi4] -> bufB natural
    {
        float2 a1 = bufA[psi4(t)],       b1 = bufA[psi4(t + 256)];
        float2 c1 = bufA[psi4(t + 512)], d1 = bufA[psi4(t + 768)];
        float2 y0, y1, y2, y3;
        bf4(a1, b1, c1, d1, Us[32 * (t >> 4)], true, y0, y1, y2, y3);
        int base = (t & 15) + 64 * (t >> 4);
        bufB[base + 0]  = y0;
        bufB[base + 16] = y1;
        bufB[base + 32] = y2;
        bufB[base + 48] = y3;
    }
    __syncthreads();

    // stage 3 (l=4, m=64): bufB -> bufA natural
    {
        float2 a1 = bufB[t],       b1 = bufB[t + 256];
        float2 c1 = bufB[t + 512], d1 = bufB[t + 768];
        float2 y0, y1, y2, y3;
        bf4(a1, b1, c1, d1, Us[128 * (t >> 6)], true, y0, y1, y2, y3);
        int base = (t & 63) + 256 * (t >> 6);
        bufA[base + 0]   = y0;
        bufA[base + 64]  = y1;
        bufA[base + 128] = y2;
        bufA[base + 192] = y3;
    }
    __syncthreads();

    // stage 4 (l=1, m=256): bufA -> bufB natural; Z in natural order
    {
        float2 a1 = bufA[t],       b1 = bufA[t + 256];
        float2 c1 = bufA[t + 512], d1 = bufA[t + 768];
        float2 y0, y1, y2, y3;
        bf4(a1, b1, c1, d1, make_float2(1.0f, 0.0f), false, y0, y1, y2, y3);
        bufB[t]       = y0;
        bufB[t + 256] = y1;
        bufB[t + 512] = y2;
        bufB[t + 768] = y3;
    }
    __syncthreads();

    // untangle + y + sum of squares
    float yv[4];
    float ssq = 0.0f;
    float y1024 = 0.0f;
    #pragma unroll
    for (int q = 0; q < 4; q++) {
        int k = t + 256 * q;
        float2 Zk = bufB[k];
        float2 Zm = bufB[(1024 - k) & 1023];
        float ReE = 0.5f * (Zk.x + Zm.x);
        float ReO = 0.5f * (Zk.y + Zm.y);
        float ImO = -0.5f * (Zk.x - Zm.x);
        float2 u = Us[k];                        // (cos, -sin)(pi k/1024)
        float yk = ReE + u.x * ReO - u.y * ImO;
        yv[q] = yk;
        ssq += 2.0f * yk * yk;
    }
    if (t == 0) {
        float2 Z0 = bufB[0];
        y1024 = Z0.x - Z0.y;
        ssq += y1024 * y1024 - yv[0] * yv[0];    // y0 counted once, add y1024
    }

    #pragma unroll
    for (int o = 16; o > 0; o >>= 1) ssq += __shfl_xor_sync(0xffffffffu, ssq, o);
    if ((t & 31) == 0) red[t >> 5] = ssq;
    __syncthreads();
    if (t == 0) {
        float s = 0.0f;
        #pragma unroll
        for (int i = 0; i < 8; i++) s += red[i];
        float mu = s_stats[0];
        float var = s * (1.0f / 2048.0f) - mu * mu;
        s_stats[1] = rsqrtf(var + EPS);
    }
    __syncthreads();

    const float mu = s_stats[0];
    const float rs = s_stats[1];
    float* orow = out + (size_t)row * CDIM;
    #pragma unroll
    for (int q = 0; q < 4; q++) {
        int k = t + 256 * q;
        float zn = (yv[q] - mu) * rs;
        orow[k] = zn * __ldg(gamma + k) + __ldg(beta + k);
        if (k > 0)
            orow[2048 - k] = zn * __ldg(gamma + 2048 - k) + __ldg(beta + 2048 - k);
    }
    if (t == 0) {
        float zn = (y1024 - mu) * rs;
        orow[1024] = zn * __ldg(gamma + 1024) + __ldg(beta + 1024);
    }
}

// ---------------------------------------------------------------- launch
extern "C" void kernel_launch(void* const* d_in, const int* in_sizes, int n_in,
                              void* d_out, int out_size) {
    const float* x     = (const float*)d_in[0];
    const float* gamma = (const float*)d_in[1];
    const float* beta  = (const float*)d_in[2];
    float* out = (float*)d_out;

    initU_kernel<<<4, 256>>>();
    fft_ln_kernel<<<ROWS, 256>>>(x, gamma, beta, out);
}

// round 12
// speedup vs baseline: 1.4588x; 1.0235x over previous
#include <cuda_runtime.h>
#include <math.h>
#include <stdint.h>

// out = LayerNorm(Re(FFT(x, axis=-1))), x: (4,4096,2048) fp32.
// One block per row. Pack x into z[n] = x[2n] + i*x[2n+1] (1024 complex),
// 1024-pt Stockham radix-4 DIF FFT (5 stages, natural order out), then
// real-FFT untangle:
//   E[k] = (Z[k] + conj(Z[-k]))/2,  O[k] = -i/2 (Z[k] - conj(Z[-k]))
//   y[k] = Re E + cos(pi k/1024) Re O + sin(pi k/1024) Im O   (k=0..1023)
//   y[1024] = Re Z[0] - Im Z[0];  y[2048-k] = y[k]
// LN: mu = x[0] (exact identity); var = mean(y^2) - mu^2 via block reduce.
// Twiddles from one table U[j] = exp(-i pi j/1024) (global init, smem copy):
//   stage twiddles w1 = U[2u], U[8(u>>2)], U[32(u>>4)], U[128(u>>6)], 1.
// Stages 0/1 write through bijective bank-spreading perms phi2/psi4.

#define ROWS 16384
#define CDIM 2048
#define EPS  1e-5f

__device__ float2 g_U[1024];

__global__ void initU_kernel() {
    int j = blockIdx.x * 256 + threadIdx.x;      // 0..1023
    float s, c;
    sincospif((float)j * (1.0f / 1024.0f), &s, &c);
    g_U[j] = make_float2(c, -s);                 // exp(-i pi j / 1024)
}

__device__ __forceinline__ float2 cmul(float2 a, float2 b) {
    return make_float2(fmaf(a.x, b.x, -a.y * b.y), fmaf(a.x, b.y, a.y * b.x));
}
__device__ __forceinline__ float2 cadd(float2 a, float2 b) { return make_float2(a.x + b.x, a.y + b.y); }
__device__ __forceinline__ float2 csub(float2 a, float2 b) { return make_float2(a.x - b.x, a.y - b.y); }

// radix-4 DIF butterfly: y_e = w1^e * (sum_q in_q * i^{-qe})
__device__ __forceinline__ void bf4(float2 a, float2 b, float2 c, float2 d,
                                    float2 w1, bool tw,
                                    float2& y0, float2& y1, float2& y2, float2& y3) {
    float2 t0 = cadd(a, c), t1 = csub(a, c);
    float2 t2 = cadd(b, d);
    float2 bd = csub(b, d);
    float2 t3 = make_float2(bd.y, -bd.x);        // -i*(b-d)
    y0 = cadd(t0, t2);
    float2 u1 = cadd(t1, t3);
    float2 u2 = csub(t0, t2);
    float2 u3 = csub(t1, t3);
    if (tw) {
        float2 w2 = cmul(w1, w1);
        float2 w3 = cmul(w2, w1);
        y1 = cmul(w1, u1);
        y2 = cmul(w2, u2);
        y3 = cmul(w3, u3);
    } else {
        y1 = u1; y2 = u2; y3 = u3;
    }
}

// Bank-spreading bijections for the two small-m stages (correct for ANY bijection).
__device__ __forceinline__ int phi2(int i) {     // stage-0 out: i = 4u + q
    return ((i & 3) << 8) | ((i >> 2) ^ ((i & 3) << 3));
}
__device__ __forceinline__ int psi4(int i) {     // stage-1 out: i = k + 4q + 16j
    int k = i & 3, q = (i >> 2) & 3;
    return (q << 8) | ((i >> 6) << 4) | ((((i >> 4) ^ q) & 3) << 2) | k;
}

__global__ __launch_bounds__(256) void fft_ln_kernel(const float* __restrict__ x,
                                                     const float* __restrict__ gamma,
                                                     const float* __restrict__ beta,
                                                     float* __restrict__ out) {
    __shared__ float2 bufA[1024];
    __shared__ float2 bufB[1024];
    __shared__ float2 Us[1024];
    __shared__ float red[8];
    __shared__ float s_stats[2];                 // [0]=mu, [1]=rs

    const int t = threadIdx.x;
    const int row = blockIdx.x;
    const float2* z = (const float2*)(x + (size_t)row * CDIM);

    #pragma unroll
    for (int q = 0; q < 4; q++) Us[t + 256 * q] = g_U[t + 256 * q];

    // stage 0 (l=256, m=1): gmem -> bufB[phi2]
    float2 a = z[t], b = z[t + 256], c = z[t + 512], d = z[t + 768];
    if (t == 0) s_stats[0] = a.x;                // mu = x[0]
    __syncthreads();                             // Us visible
    {
        float2 y0, y1, y2, y3;
        bf4(a, b, c, d, Us[2 * t], true, y0, y1, y2, y3);
        int base = 4 * t;
        bufB[phi2(base + 0)] = y0;
        bufB[phi2(base + 1)] = y1;
        bufB[phi2(base + 2)] = y2;
        bufB[phi2(base + 3)] = y3;
    }
    __syncthreads();

    // stage 1 (l=64, m=4): bufB[phi2] -> bufA[psi4]
    {
        float2 a1 = bufB[phi2(t)],       b1 = bufB[phi2(t + 256)];
        float2 c1 = bufB[phi2(t + 512)], d1 = bufB[phi2(t + 768)];
        float2 y0, y1, y2, y3;
        bf4(a1, b1, c1, d1, Us[8 * (t >> 2)], true, y0, y1, y2, y3);
        int base = (t & 3) + 16 * (t >> 2);      // k + 16 j
        bufA[psi4(base + 0)]  = y0;
        bufA[psi4(base + 4)]  = y1;
        bufA[psi4(base + 8)]  = y2;
        bufA[psi4(base + 12)] = y3;
    }
    __syncthreads();

    // stage 2 (l=16, m=16): bufA[psi4] -> bufB natural
    {
        float2 a1 = bufA[psi4(t)],       b1 = bufA[psi4(t + 256)];
        float2 c1 = bufA[psi4(t + 512)], d1 = bufA[psi4(t + 768)];
        float2 y0, y1, y2, y3;
        bf4(a1, b1, c1, d1, Us[32 * (t >> 4)], true, y0, y1, y2, y3);
        int base = (t & 15) + 64 * (t >> 4);
        bufB[base + 0]  = y0;
        bufB[base + 16] = y1;
        bufB[base + 32] = y2;
        bufB[base + 48] = y3;
    }
    __syncthreads();

    // stage 3 (l=4, m=64): bufB -> bufA natural
    {
        float2 a1 = bufB[t],       b1 = bufB[t + 256];
        float2 c1 = bufB[t + 512], d1 = bufB[t + 768];
        float2 y0, y1, y2, y3;
        bf4(a1, b1, c1, d1, Us[128 * (t >> 6)], true, y0, y1, y2, y3);
        int base = (t & 63) + 256 * (t >> 6);
        bufA[base + 0]   = y0;
        bufA[base + 64]  = y1;
        bufA[base + 128] = y2;
        bufA[base + 192] = y3;
    }
    __syncthreads();

    // stage 4 (l=1, m=256): bufA -> bufB natural; Z in natural order
    {
        float2 a1 = bufA[t],       b1 = bufA[t + 256];
        float2 c1 = bufA[t + 512], d1 = bufA[t + 768];
        float2 y0, y1, y2, y3;
        bf4(a1, b1, c1, d1, make_float2(1.0f, 0.0f), false, y0, y1, y2, y3);
        bufB[t]       = y0;
        bufB[t + 256] = y1;
        bufB[t + 512] = y2;
        bufB[t + 768] = y3;
    }
    __syncthreads();

    // untangle + y + sum of squares
    float yv[4];
    float ssq = 0.0f;
    float y1024 = 0.0f;
    #pragma unroll
    for (int q = 0; q < 4; q++) {
        int k = t + 256 * q;
        float2 Zk = bufB[k];
        float2 Zm = bufB[(1024 - k) & 1023];
        float ReE = 0.5f * (Zk.x + Zm.x);
        float ReO = 0.5f * (Zk.y + Zm.y);
        float ImO = -0.5f * (Zk.x - Zm.x);
        float2 u = Us[k];                        // (cos, -sin)(pi k/1024)
        float yk = ReE + u.x * ReO - u.y * ImO;
        yv[q] = yk;
        ssq += 2.0f * yk * yk;
    }
    if (t == 0) {
        float2 Z0 = bufB[0];
        y1024 = Z0.x - Z0.y;
        ssq += y1024 * y1024 - yv[0] * yv[0];    // y0 counted once, add y1024
    }

    #pragma unroll
    for (int o = 16; o > 0; o >>= 1) ssq += __shfl_xor_sync(0xffffffffu, ssq, o);
    if ((t & 31) == 0) red[t >> 5] = ssq;
    __syncthreads();
    if (t == 0) {
        float s = 0.0f;
        #pragma unroll
        for (int i = 0; i < 8; i++) s += red[i];
        float mu = s_stats[0];
        float var = s * (1.0f / 2048.0f) - mu * mu;
        s_stats[1] = rsqrtf(var + EPS);
    }
    __syncthreads();

    const float mu = s_stats[0];
    const float rs = s_stats[1];
    float* orow = out + (size_t)row * CDIM;
    #pragma unroll
    for (int q = 0; q < 4; q++) {
        int k = t + 256 * q;
        float zn = (yv[q] - mu) * rs;
        orow[k] = zn * __ldg(gamma + k) + __ldg(beta + k);
        if (k > 0)
            orow[2048 - k] = zn * __ldg(gamma + 2048 - k) + __ldg(beta + 2048 - k);
    }
    if (t == 0) {
        float zn = (y1024 - mu) * rs;
        orow[1024] = zn * __ldg(gamma + 1024) + __ldg(beta + 1024);
    }
}

// ---------------------------------------------------------------- launch
extern "C" void kernel_launch(void* const* d_in, const int* in_sizes, int n_in,
                              void* d_out, int out_size) {
    const float* x     = (const float*)d_in[0];
    const float* gamma = (const float*)d_in[1];
    const float* beta  = (const float*)d_in[2];
    float* out = (float*)d_out;

    initU_kernel<<<4, 256>>>();
    fft_ln_kernel<<<ROWS, 256>>>(x, gamma, beta, out);
}

// round 13
// speedup vs baseline: 2.1377x; 1.4653x over previous
#include <cuda_runtime.h>
#include <math.h>
#include <stdint.h>

// out = LayerNorm(Re(FFT(x, axis=-1))), x: (4,4096,2048) fp32.
// Pack z[n] = x[2n] + i x[2n+1] (1024 complex). 4-step CT: 1024 = 32 x 32,
// one WARP per row, 32 complex per lane:
//   r[j] = z[u + 32 j]                      (lane u = n2)
//   FFT32 over j (regs)  -> A[k1] at r[brev5(k1)]
//   r *= W_1024^{u * k1}                    (register recurrence from U[2u])
//   smem transpose -> lane u = k1 holds A'[k1][n2], n2 natural
//   FFT32 over n2 (regs) -> Z[u + 32 k2] at r[brev5(k2)]
// Untangle (shuffle with lane (32-u)&31; reg index 31-i; lane-0 const table):
//   y[k] = ReE + cos(pi k/1024) ReO + sin(pi k/1024) ImO,  y[2048-k] = y[k]
//   y[1024] = Re Z0 - Im Z0;  mu = x[0];  var = mean(y^2) - mu^2 (warp reduce)
// No __syncthreads after the twiddle-table copy: each warp fully independent.

#define ROWS 16384
#define CDIM 2048
#define EPS  1e-5f
#define FULL 0xffffffffu

__device__ float2 g_U[1024];   // U[j] = exp(-i pi j/1024) = (cos, -sin)

__global__ void initU_kernel() {
    int j = blockIdx.x * 256 + threadIdx.x;
    float s, c;
    sincospif((float)j * (1.0f / 1024.0f), &s, &c);
    g_U[j] = make_float2(c, -s);
}

__device__ __forceinline__ float2 cmul(float2 a, float2 b) {
    return make_float2(fmaf(a.x, b.x, -a.y * b.y), fmaf(a.x, b.y, a.y * b.x));
}

__host__ __device__ constexpr int brev5(int i) {
    return ((i & 1) << 4) | ((i & 2) << 2) | (i & 4) | ((i & 8) >> 2) | ((i & 16) >> 4);
}
// lane-0 self-pair map: k2 = brev5(i), k2' = (32-k2)&31, return brev5(k2')
__host__ __device__ constexpr int l0map(int i) {
    return brev5((32 - brev5(i)) & 31);
}

// 32-pt DIF FFT (Gentleman-Sande), output bit-reversed: r[i] = X[brev5(i)].
__device__ __forceinline__ void fft32(float2* r) {
    const float CR[16] = { 1.0f, 0.98078528f, 0.92387953f, 0.83146961f,
                           0.70710678f, 0.55557023f, 0.38268343f, 0.19509032f,
                           0.0f, -0.19509032f, -0.38268343f, -0.55557023f,
                           -0.70710678f, -0.83146961f, -0.92387953f, -0.98078528f };
    const float CI[16] = { 0.0f, -0.19509032f, -0.38268343f, -0.55557023f,
                           -0.70710678f, -0.83146961f, -0.92387953f, -0.98078528f,
                           -1.0f, -0.98078528f, -0.92387953f, -0.83146961f,
                           -0.70710678f, -0.55557023f, -0.38268343f, -0.19509032f };
    #pragma unroll
    for (int half = 16; half >= 1; half >>= 1) {
        #pragma unroll
        for (int g = 0; g < 32; g += 2 * half) {
            #pragma unroll
            for (int j = 0; j < half; j++) {
                float2 a = r[g + j], b = r[g + j + half];
                r[g + j] = make_float2(a.x + b.x, a.y + b.y);
                float dx = a.x - b.x, dy = a.y - b.y;
                int tw = j * (16 / half);
                if (tw == 0) r[g + j + half] = make_float2(dx, dy);
                else r[g + j + half] = make_float2(fmaf(dx, CR[tw], -dy * CI[tw]),
                                                   fmaf(dx, CI[tw],  dy * CR[tw]));
            }
        }
    }
}

__global__ void __launch_bounds__(128, 4) fft_ln_kernel(const float* __restrict__ x,
                                                        const float* __restrict__ gamma,
                                                        const float* __restrict__ beta,
                                                        float* __restrict__ out) {
    __shared__ float Sx[4][33 * 32];
    __shared__ float Sy[4][33 * 32];
    __shared__ float2 Us[1024];

    const int t = threadIdx.x;
    const int w = t >> 5;
    const int u = t & 31;

    #pragma unroll
    for (int q = 0; q < 8; q++) Us[t + 128 * q] = g_U[t + 128 * q];
    __syncthreads();

    const int row = blockIdx.x * 4 + w;
    const float2* z = (const float2*)(x + (size_t)row * CDIM);

    float2 r[32];
    #pragma unroll
    for (int j = 0; j < 32; j++) r[j] = z[u + 32 * j];
    const float mu = __shfl_sync(FULL, r[0].x, 0);

    fft32(r);

    // twiddle r[brev5(c)] *= W_1024^{u*c}, 4 independent 8-step chains
    {
        float2 wstep = Us[2 * u];                       // W_1024^u
        float2 w2 = cmul(wstep, wstep);
        float2 w4 = cmul(w2, w2);
        float2 w8 = cmul(w4, w4);
        float2 w16 = cmul(w8, w8);
        float2 base[4] = { make_float2(1.0f, 0.0f), w8, w16, cmul(w16, w8) };
        #pragma unroll
        for (int q = 0; q < 4; q++) {
            float2 wc = base[q];
            #pragma unroll
            for (int j = 0; j < 8; j++) {
                int c = 8 * q + j;
                r[brev5(c)] = cmul(r[brev5(c)], wc);
                wc = cmul(wc, wstep);
            }
        }
    }

    // transpose: lane u=n2 rows -> lane u=k1 rows
    float* sx = Sx[w];
    float* sy = Sy[w];
    #pragma unroll
    for (int i = 0; i < 32; i++) {
        int k1 = brev5(i);
        sx[k1 * 33 + u] = r[i].x;
        sy[k1 * 33 + u] = r[i].y;
    }
    __syncwarp();
    #pragma unroll
    for (int j = 0; j < 32; j++) {
        r[j].x = sx[u * 33 + j];
        r[j].y = sy[u * 33 + j];
    }
    __syncwarp();

    fft32(r);                                           // r[i] = Z[u + 32*brev5(i)]

    // untangle + y + sum of squares; stage y in (now free) Sx
    float ssq = 0.0f, y1024 = 0.0f;
    const int partner = (32 - u) & 31;
    float* Y = sx;
    #pragma unroll
    for (int i = 0; i < 32; i++) {
        float2 Zk = r[i];
        float2 sd = r[31 - i];
        float zmx = __shfl_sync(FULL, sd.x, partner);
        float zmy = __shfl_sync(FULL, sd.y, partner);
        if (u == 0) { zmx = r[l0map(i)].x; zmy = r[l0map(i)].y; }
        float2 uk = Us[u + (brev5(i) << 5)];            // (cos, -sin)(pi k/1024)
        float ReE = 0.5f * (Zk.x + zmx);
        float ReO = 0.5f * (Zk.y + zmy);
        float ImO = -0.5f * (Zk.x - zmx);
        float yk = ReE + uk.x * ReO - uk.y * ImO;
        Y[i * 32 + u] = yk;
        ssq += 2.0f * yk * yk;
        if (i == 0 && u == 0) {
            y1024 = Zk.x - Zk.y;
            ssq += y1024 * y1024 - yk * yk;
        }
    }
    __syncwarp();

    #pragma unroll
    for (int o = 16; o > 0; o >>= 1) ssq += __shfl_xor_sync(FULL, ssq, o);
    const float var = ssq * (1.0f / 2048.0f) - mu * mu;
    const float rs = rsqrtf(var + EPS);

    float* orow = out + (size_t)row * CDIM;
    #pragma unroll
    for (int i = 0; i < 32; i++) {
        int k = u + (brev5(i) << 5);
        float zn = (Y[i * 32 + u] - mu) * rs;
        orow[k] = zn * __ldg(gamma + k) + __ldg(beta + k);
        if (k > 0)
            orow[2048 - k] = zn * __ldg(gamma + 2048 - k) + __ldg(beta + 2048 - k);
    }
    if (u == 0) {
        float zn = (y1024 - mu) * rs;
        orow[1024] = zn * __ldg(gamma + 1024) + __ldg(beta + 1024);
    }
}

// ---------------------------------------------------------------- launch
extern "C" void kernel_launch(void* const* d_in, const int* in_sizes, int n_in,
                              void* d_out, int out_size) {
    const float* x     = (const float*)d_in[0];
    const float* gamma = (const float*)d_in[1];
    const float* beta  = (const float*)d_in[2];
    float* out = (float*)d_out;

    initU_kernel<<<4, 256>>>();
    fft_ln_kernel<<<ROWS / 4, 128>>>(x, gamma, beta, out);
}